// round 14
// baseline (speedup 1.0000x reference)
#include <cuda_runtime.h>
#include <cuda_bf16.h>

#define KK 26
#define DD 128
#define MM 256
#define BB 512
#define NRED 126         // reducer blocks (126*32 >= 4004 outputs)
#define KP 28            // padded row stride; rows 112B -> 16B-aligned (LDS.128-able)
#define WPAD 130         // padded W row stride (conflict-free LDS.64 per 16-lane phase)
#define OUTSZ (KK*DD + KK*KK)   // 4004

typedef unsigned long long u64;

__device__ float g_scratch[BB * OUTSZ];   // per-word gradients
__device__ int g_ctr  = 0;                // word-completion doorbell
__device__ int g_done = 0;                // reducer-completion counter

// ---- packed f32x2 helpers (FFMA2 path, sm_100a) ----
__device__ __forceinline__ u64 ffma2(u64 a, u64 b, u64 c) {
    u64 d;
    asm("fma.rn.f32x2 %0, %1, %2, %3;" : "=l"(d) : "l"(a), "l"(b), "l"(c));
    return d;
}
__device__ __forceinline__ u64 pk2(float lo, float hi) {
    u64 r; asm("mov.b64 %0, {%1, %2};" : "=l"(r) : "f"(lo), "f"(hi)); return r;
}
__device__ __forceinline__ float2 upk2(u64 v) {
    float2 f; asm("mov.b64 {%0, %1}, %2;" : "=f"(f.x), "=f"(f.y) : "l"(v)); return f;
}
__device__ __forceinline__ int ld_vol(const int* p) {
    int v; asm volatile("ld.volatile.global.s32 %0, [%1];" : "=r"(v) : "l"(p)); return v;
}

// ---- dynamic shared memory layout (floats) ----
#define SM_PS   0                      // [MM][KP] Ps, later Rres
#define SM_U    (SM_PS + MM*KP)        // [MM][KP] U,  later A
#define SM_V    (SM_U  + MM*KP)        // [MM][KP] V,  later B  (aliases Wsh in phase S)
#define SM_E    (SM_V  + MM*KP)        // [KK*KK]  exp(T)
#define SM_LAB  (SM_E  + KK*KK)        // [MM] int labels
#define SM_DEXP (SM_LAB + MM)          // [MM] int backward scale exponents
#define SM_CNT  (SM_DEXP + MM)         // [KK*KK] int transition counts
#define SM_TOT  (SM_CNT + KK*KK)       // 23368 floats = 93472 bytes

__global__ void __launch_bounds__(256, 2)
crf_fused_kernel(const float* __restrict__ data,
                 const int* __restrict__ labI,
                 const float* __restrict__ Wg,
                 const float* __restrict__ Tg,
                 float* __restrict__ out)
{
    extern __shared__ float sm[];
    const int t    = threadIdx.x;
    const int lane = t & 31;
    const int wid  = t >> 5;

    // ================= REDUCER BLOCKS =================
    if (blockIdx.x >= BB) {
        if (t == 0) {
            while (ld_vol(&g_ctr) < BB) __nanosleep(200);
        }
        __syncthreads();
        __threadfence();   // acquire: order scratch reads after doorbell

        float* red = sm;   // [8][33]
        const int ws = wid;
        const int og = (blockIdx.x - BB) * 32 + lane;
        float s0 = 0.f, s1 = 0.f, s2 = 0.f, s3 = 0.f;
        if (og < OUTSZ) {
            const float* p = g_scratch + (size_t)ws * 64 * OUTSZ + og;
            #pragma unroll 4
            for (int v = 0; v < 64; v += 4) {
                s0 += p[(size_t)(v + 0) * OUTSZ];
                s1 += p[(size_t)(v + 1) * OUTSZ];
                s2 += p[(size_t)(v + 2) * OUTSZ];
                s3 += p[(size_t)(v + 3) * OUTSZ];
            }
        }
        red[ws * 33 + lane] = (s0 + s1) + (s2 + s3);
        __syncthreads();
        if (ws == 0 && og < OUTSZ) {
            float tot = 0.f;
            #pragma unroll
            for (int j = 0; j < 8; ++j) tot += red[j * 33 + lane];
            out[og] = tot * (1.0f / BB);
        }
        __threadfence();
        __syncthreads();
        if (t == 0) {
            if (atomicAdd(&g_done, 1) == NRED - 1) {   // last reducer resets for replay
                g_ctr  = 0;
                g_done = 0;
            }
        }
        return;
    }

    // ================= WORD BLOCKS =================
    float* Ps  = sm + SM_PS;
    float* U   = sm + SM_U;
    float* V   = sm + SM_V;
    float* Wsh = sm + SM_V;            // alias: W lives here only during phase S
    float* E   = sm + SM_E;
    int*   lab  = (int*)(sm + SM_LAB);
    int*   dexp = (int*)(sm + SM_DEXP);
    int*   cnt  = (int*)(sm + SM_CNT);
    __shared__ int s_is64;

    const int w = blockIdx.x;

    // ---- detect labels dtype (int64 little-endian -> odd int32 words all zero) ----
    if (t == 0) s_is64 = 1;
    __syncthreads();
    if (labI[2*t + 1] != 0) atomicAnd(&s_is64, 0);

    // ---- init: E = exp(T), W -> padded smem, zero counts + dexp ----
    for (int p = t; p < KK*KK; p += 256) { E[p] = __expf(Tg[p]); cnt[p] = 0; }
    for (int p = t; p < KK*DD; p += 256) Wsh[(p / DD) * WPAD + (p % DD)] = Wg[p];
    for (int p = t; p < MM;    p += 256) dexp[p] = 0;
    __syncthreads();
    const int is64 = s_is64;
    for (int p = t; p < MM; p += 256)
        lab[p] = is64 ? labI[((size_t)w*MM + p) * 2] : labI[(size_t)w*MM + p];
    __syncthreads();
    if (t < MM - 1) atomicAdd(&cnt[lab[t]*KK + lab[t+1]], 1);   // exact int, deterministic

    // ---- Phase S: Ps[i][k] = exp(dot(x[i], W[k])) -- 8 rows per W pass ----
    const float* x = data + (size_t)w * MM * DD;
    {
        const int ll = (lane < KK) ? lane : 0;
        const u64* wr = (const u64*)(Wsh + ll * WPAD);
        const int i0 = wid * 32;
        for (int g = 0; g < 4; ++g) {
            const int ib = i0 + g * 8;
            const double2* xb = (const double2*)(x + (size_t)ib * DD);  // row stride DD/4 double2
            u64 acc[8];
            #pragma unroll
            for (int r = 0; r < 8; ++r) acc[r] = 0;
            #pragma unroll 4
            for (int p = 0; p < DD/4; ++p) {
                u64 w0 = wr[2*p], w1 = wr[2*p + 1];
                #pragma unroll
                for (int r = 0; r < 8; ++r) {
                    double2 v = __ldg(xb + (size_t)r * (DD/4) + p);  // 16B lane-uniform broadcast
                    acc[r] = ffma2((u64)__double_as_longlong(v.x), w0, acc[r]);
                    acc[r] = ffma2((u64)__double_as_longlong(v.y), w1, acc[r]);
                }
            }
            if (lane < KK) {
                #pragma unroll
                for (int r = 0; r < 8; ++r) {
                    float2 f = upk2(acc[r]);
                    Ps[(ib + r)*KP + lane] = __expf(f.x + f.y);
                }
            }
        }
    }
    __syncthreads();   // Ps done; Wsh region now free for V

    // ---- Phase DP: warp0 forward, warp1 backward (linear domain, renorm every 4) ----
    if (wid == 0) {
        const int ll = (lane < KK) ? lane : 0;
        float Ecol[KK];
        #pragma unroll
        for (int j = 0; j < KK; ++j) Ecol[j] = E[j*KK + ll];   // E[y', lane]
        float u = (lane < KK) ? 1.f : 0.f;
        if (lane < KK) U[lane] = 1.f;
        float pcur = Ps[ll];
        for (int i = 1; i < MM; ++i) {
            float tv = (lane < KK) ? u * pcur : 0.f;
            pcur = Ps[i*KP + ll];                     // prefetch row i (used next iter)
            float a0 = 0.f, a1 = 0.f, a2 = 0.f, a3 = 0.f;
            #pragma unroll
            for (int j = 0; j < 24; j += 4) {
                a0 = fmaf(__shfl_sync(0xffffffffu, tv, j+0), Ecol[j+0], a0);
                a1 = fmaf(__shfl_sync(0xffffffffu, tv, j+1), Ecol[j+1], a1);
                a2 = fmaf(__shfl_sync(0xffffffffu, tv, j+2), Ecol[j+2], a2);
                a3 = fmaf(__shfl_sync(0xffffffffu, tv, j+3), Ecol[j+3], a3);
            }
            a0 = fmaf(__shfl_sync(0xffffffffu, tv, 24), Ecol[24], a0);
            a1 = fmaf(__shfl_sync(0xffffffffu, tv, 25), Ecol[25], a1);
            float un = (a0 + a1) + (a2 + a3);
            if ((i & 3) == 0) {                       // exact 2^k renorm, every 4 steps
                unsigned mb = __reduce_max_sync(0xffffffffu, __float_as_uint(un));
                un *= __uint_as_float((254u - (mb >> 23)) << 23);
            }
            u = un;
            if (lane < KK) U[i*KP + lane] = u;
        }
    } else if (wid == 1) {
        const int ll = (lane < KK) ? lane : 0;
        float Erow[KK];
        #pragma unroll
        for (int j = 0; j < KK; ++j) Erow[j] = E[ll*KK + j];   // E[lane, y'']
        float v = (lane < KK) ? 1.f : 0.f;
        if (lane < KK) V[(MM-1)*KP + lane] = 1.f;
        float pcur = Ps[(MM-1)*KP + ll];
        for (int i = MM - 2; i >= 0; --i) {
            float rv = (lane < KK) ? v * pcur : 0.f;
            pcur = Ps[i*KP + ll];                     // prefetch row i (used next iter)
            float a0 = 0.f, a1 = 0.f, a2 = 0.f, a3 = 0.f;
            #pragma unroll
            for (int j = 0; j < 24; j += 4) {
                a0 = fmaf(__shfl_sync(0xffffffffu, rv, j+0), Erow[j+0], a0);
                a1 = fmaf(__shfl_sync(0xffffffffu, rv, j+1), Erow[j+1], a1);
                a2 = fmaf(__shfl_sync(0xffffffffu, rv, j+2), Erow[j+2], a2);
                a3 = fmaf(__shfl_sync(0xffffffffu, rv, j+3), Erow[j+3], a3);
            }
            a0 = fmaf(__shfl_sync(0xffffffffu, rv, 24), Erow[24], a0);
            a1 = fmaf(__shfl_sync(0xffffffffu, rv, 25), Erow[25], a1);
            float vn = (a0 + a1) + (a2 + a3);
            if ((i & 3) == 0) {
                unsigned mb = __reduce_max_sync(0xffffffffu, __float_as_uint(vn));
                int fe = (int)(mb >> 23);
                vn *= __uint_as_float((unsigned)(254 - fe) << 23);
                if (lane == 0) dexp[i] = fe - 127;    // applied exponent e_i (else 0)
            }
            v = vn;
            if (lane < KK) V[i*KP + lane] = v;
        }
    }
    __syncthreads();

    // ---- Residual pass: Rres -> Ps, A -> U, B -> V (in place, per-row) ----
    for (int r = 0; r < MM/8; ++r) {
        const int i = wid * (MM/8) + r;
        float u_ = 0.f, v_ = 0.f, p_ = 0.f, prod = 0.f;
        if (lane < KK) {
            u_ = U[i*KP + lane]; v_ = V[i*KP + lane]; p_ = Ps[i*KP + lane];
            prod = u_ * v_ * p_;
        }
        float z = prod;
        #pragma unroll
        for (int o = 16; o; o >>= 1) z += __shfl_xor_sync(0xffffffffu, z, o);
        float inv = 1.f / z;                           // 1 / z_i
        if (lane < KK) {
            float p1 = prod * inv;
            float oh = (lab[i] == lane) ? 1.f : 0.f;
            float sc = __uint_as_float((unsigned)(127 - dexp[i]) << 23);  // exact 2^-e
            Ps[i*KP + lane] = oh - p1;                 // Rres
            U[i*KP + lane]  = u_ * p_ * inv * sc;      // A
            V[i*KP + lane]  = p_ * v_;                 // B
        }
    }
    __syncthreads();

    float* outw = g_scratch + (size_t)w * OUTSZ;

    // ---- dT: counts - E .* sum_i A[i]^T B[i+1] (packed over b-pairs) ----
    for (int pp = t; pp < (KK*KK)/2; pp += 256) {
        const int a = pp / (KK/2);
        const int q = pp - a * (KK/2);                 // b pair = (2q, 2q+1)
        u64 s2 = 0;
        const float* Ua = U + a;
        const u64*   Vq = (const u64*)(V + 2*q);       // row i at offset i*(KP/2)
        #pragma unroll 4
        for (int i = 0; i < MM - 1; ++i) {
            float uu = Ua[i*KP];
            s2 = ffma2(pk2(uu, uu), Vq[(i+1)*(KP/2)], s2);
        }
        float2 s = upk2(s2);
        const int b0 = 2*q;
        outw[KK*DD + a*KK + b0]     = (float)cnt[a*KK + b0]     - E[a*KK + b0]     * s.x;
        outw[KK*DD + a*KK + b0 + 1] = (float)cnt[a*KK + b0 + 1] - E[a*KK + b0 + 1] * s.y;
    }

    // ---- dw: Rres^T @ x -- quad broadcast reads (3x LDS.128 + half*LDS.64 per row) ----
    // half0: pairs 0-5 (k 0..11, floats 0-11); half1: pairs 6-12 (k 12..25, floats 12-25).
    // Row base = 112*i bytes (16B-aligned); half1 offset 48B, extra pair at 96B: all aligned.
    {
        const int d    = t & (DD - 1);
        const int half = t >> 7;
        const int off  = half * 12;                    // float offset of this half's quads
        u64 acc[7];
        #pragma unroll
        for (int j = 0; j < 7; ++j) acc[j] = 0;
        const float* xp = x + d;
        #pragma unroll 2
        for (int i = 0; i < MM; ++i) {
            float xv = __ldg(xp + (size_t)i * DD);     // coalesced across lanes
            u64 xx = pk2(xv, xv);
            const float* row = Ps + i*KP + off;
            ulonglong2 qA = *(const ulonglong2*)(row);      // pairs off/2+0, +1
            ulonglong2 qB = *(const ulonglong2*)(row + 4);  // pairs +2, +3
            ulonglong2 qC = *(const ulonglong2*)(row + 8);  // pairs +4, +5
            acc[0] = ffma2(qA.x, xx, acc[0]);
            acc[1] = ffma2(qA.y, xx, acc[1]);
            acc[2] = ffma2(qB.x, xx, acc[2]);
            acc[3] = ffma2(qB.y, xx, acc[3]);
            acc[4] = ffma2(qC.x, xx, acc[4]);
            acc[5] = ffma2(qC.y, xx, acc[5]);
            if (half) {                                 // pair 12 (k 24,25) at float 24
                u64 ex = *(const u64*)(Ps + i*KP + 24);
                acc[6] = ffma2(ex, xx, acc[6]);
            }
        }
        const int np = 6 + half;
        #pragma unroll
        for (int j = 0; j < 7; ++j) {
            if (j < np) {
                float2 f = upk2(acc[j]);
                const int k = half * 12 + 2 * j;
                outw[(k)     * DD + d] = f.x;
                outw[(k + 1) * DD + d] = f.y;
            }
        }
    }

    // ---- doorbell: this word's gradients are globally visible ----
    __syncthreads();
    if (t == 0) {
        __threadfence();              // release scratch writes
        atomicAdd(&g_ctr, 1);
    }
}

extern "C" void kernel_launch(void* const* d_in, const int* in_sizes, int n_in,
                              void* d_out, int out_size)
{
    const float* data   = (const float*)d_in[0];
    const int*   labels = (const int*)d_in[1];
    const float* W      = (const float*)d_in[2];
    const float* T      = (const float*)d_in[3];
    float* out = (float*)d_out;

    const size_t smem = SM_TOT * sizeof(float);
    cudaFuncSetAttribute(crf_fused_kernel,
                         cudaFuncAttributeMaxDynamicSharedMemorySize, (int)smem);
    crf_fused_kernel<<<BB + NRED, 256, smem>>>(data, labels, W, T, out);
}

// round 15
// speedup vs baseline: 1.0487x; 1.0487x over previous
#include <cuda_runtime.h>
#include <cuda_bf16.h>

#define KK 26
#define DD 128
#define MM 256
#define BB 512
#define NRED 126         // reducer blocks (126*32 >= 4004 outputs)
#define NT  384          // threads per block (12 warps)
#define NW  12
#define KP 28            // padded row stride (8B-aligned rows); 2x93.5KB keeps L1D carveout
#define WPAD 130         // padded W row stride (conflict-free LDS.64 per 16-lane phase)
#define OUTSZ (KK*DD + KK*KK)   // 4004

typedef unsigned long long u64;

__device__ float g_scratch[BB * OUTSZ];   // per-word gradients
__device__ int g_ctr  = 0;                // word-completion doorbell
__device__ int g_done = 0;                // reducer-completion counter

// ---- packed f32x2 helpers (FFMA2 path, sm_100a) ----
__device__ __forceinline__ u64 ffma2(u64 a, u64 b, u64 c) {
    u64 d;
    asm("fma.rn.f32x2 %0, %1, %2, %3;" : "=l"(d) : "l"(a), "l"(b), "l"(c));
    return d;
}
__device__ __forceinline__ u64 pk2(float lo, float hi) {
    u64 r; asm("mov.b64 %0, {%1, %2};" : "=l"(r) : "f"(lo), "f"(hi)); return r;
}
__device__ __forceinline__ float2 upk2(u64 v) {
    float2 f; asm("mov.b64 {%0, %1}, %2;" : "=f"(f.x), "=f"(f.y) : "l"(v)); return f;
}
__device__ __forceinline__ int ld_vol(const int* p) {
    int v; asm volatile("ld.volatile.global.s32 %0, [%1];" : "=r"(v) : "l"(p)); return v;
}

// ---- dynamic shared memory layout (floats) ----
#define SM_PS   0                      // [MM][KP] Ps, later Rres
#define SM_U    (SM_PS + MM*KP)        // [MM][KP] U,  later A
#define SM_V    (SM_U  + MM*KP)        // [MM][KP] V,  later B  (aliases Wsh in phase S)
#define SM_E    (SM_V  + MM*KP)        // [KK*KK]  exp(T)
#define SM_LAB  (SM_E  + KK*KK)        // [MM] int labels
#define SM_DEXP (SM_LAB + MM)          // [MM] int backward scale exponents
#define SM_CNT  (SM_DEXP + MM)         // [KK*KK] int transition counts
#define SM_TOT  (SM_CNT + KK*KK)       // 23368 floats = 93472 bytes

__global__ void __launch_bounds__(NT, 2)
crf_fused_kernel(const float* __restrict__ data,
                 const int* __restrict__ labI,
                 const float* __restrict__ Wg,
                 const float* __restrict__ Tg,
                 float* __restrict__ out)
{
    extern __shared__ float sm[];
    const int t    = threadIdx.x;
    const int lane = t & 31;
    const int wid  = t >> 5;

    // ================= REDUCER BLOCKS =================
    if (blockIdx.x >= BB) {
        if (t == 0) {
            while (ld_vol(&g_ctr) < BB) __nanosleep(200);
        }
        __syncthreads();
        __threadfence();   // acquire: order scratch reads after doorbell

        float* red = sm;   // [8][33]
        const int ws = wid;
        const int og = (blockIdx.x - BB) * 32 + lane;
        if (ws < 8) {
            float s0 = 0.f, s1 = 0.f, s2 = 0.f, s3 = 0.f;
            if (og < OUTSZ) {
                const float* p = g_scratch + (size_t)ws * 64 * OUTSZ + og;
                #pragma unroll 4
                for (int v = 0; v < 64; v += 4) {
                    s0 += p[(size_t)(v + 0) * OUTSZ];
                    s1 += p[(size_t)(v + 1) * OUTSZ];
                    s2 += p[(size_t)(v + 2) * OUTSZ];
                    s3 += p[(size_t)(v + 3) * OUTSZ];
                }
            }
            red[ws * 33 + lane] = (s0 + s1) + (s2 + s3);
        }
        __syncthreads();
        if (ws == 0 && og < OUTSZ) {
            float tot = 0.f;
            #pragma unroll
            for (int j = 0; j < 8; ++j) tot += red[j * 33 + lane];
            out[og] = tot * (1.0f / BB);
        }
        __threadfence();
        __syncthreads();
        if (t == 0) {
            if (atomicAdd(&g_done, 1) == NRED - 1) {   // last reducer resets for replay
                g_ctr  = 0;
                g_done = 0;
            }
        }
        return;
    }

    // ================= WORD BLOCKS =================
    float* Ps  = sm + SM_PS;
    float* U   = sm + SM_U;
    float* V   = sm + SM_V;
    float* Wsh = sm + SM_V;            // alias: W lives here only during phase S
    float* E   = sm + SM_E;
    int*   lab  = (int*)(sm + SM_LAB);
    int*   dexp = (int*)(sm + SM_DEXP);
    int*   cnt  = (int*)(sm + SM_CNT);
    __shared__ int s_is64;

    const int w = blockIdx.x;

    // ---- detect labels dtype (int64 LE -> odd int32 words of non-negative labels are 0) ----
    if (t == 0) s_is64 = 1;
    __syncthreads();
    if (labI[2*t + 1] != 0) atomicAnd(&s_is64, 0);   // t<384: indices <768, always in-bounds

    // ---- init: E = exp(T), W -> padded smem, zero counts + dexp ----
    for (int p = t; p < KK*KK; p += NT) { E[p] = __expf(Tg[p]); cnt[p] = 0; }
    for (int p = t; p < KK*DD; p += NT) Wsh[(p / DD) * WPAD + (p % DD)] = Wg[p];
    for (int p = t; p < MM;    p += NT) dexp[p] = 0;
    __syncthreads();
    const int is64 = s_is64;
    for (int p = t; p < MM; p += NT)
        lab[p] = is64 ? labI[((size_t)w*MM + p) * 2] : labI[(size_t)w*MM + p];
    __syncthreads();
    if (t < MM - 1) atomicAdd(&cnt[lab[t]*KK + lab[t+1]], 1);   // exact int, deterministic

    // ---- Phase S: Ps[i][k] = exp(dot(x[i], W[k])) -- 8 rows per W pass, 12 warps ----
    const float* x = data + (size_t)w * MM * DD;
    {
        const int ll = (lane < KK) ? lane : 0;
        const u64* wr = (const u64*)(Wsh + ll * WPAD);
        for (int g = wid; g < 32; g += NW) {           // 32 groups of 8 rows
            const int ib = g * 8;
            const double2* xb = (const double2*)(x + (size_t)ib * DD);  // row stride DD/4 double2
            u64 acc[8];
            #pragma unroll
            for (int r = 0; r < 8; ++r) acc[r] = 0;
            #pragma unroll 4
            for (int p = 0; p < DD/4; ++p) {
                u64 w0 = wr[2*p], w1 = wr[2*p + 1];
                #pragma unroll
                for (int r = 0; r < 8; ++r) {
                    double2 v = __ldg(xb + (size_t)r * (DD/4) + p);  // 16B lane-uniform broadcast
                    acc[r] = ffma2((u64)__double_as_longlong(v.x), w0, acc[r]);
                    acc[r] = ffma2((u64)__double_as_longlong(v.y), w1, acc[r]);
                }
            }
            if (lane < KK) {
                #pragma unroll
                for (int r = 0; r < 8; ++r) {
                    float2 f = upk2(acc[r]);
                    Ps[(ib + r)*KP + lane] = __expf(f.x + f.y);
                }
            }
        }
    }
    __syncthreads();   // Ps done; Wsh region now free for V

    // ---- Phase DP: warp0 forward, warp1 backward (linear domain, renorm every 4) ----
    if (wid == 0) {
        const int ll = (lane < KK) ? lane : 0;
        float Ecol[KK];
        #pragma unroll
        for (int j = 0; j < KK; ++j) Ecol[j] = E[j*KK + ll];   // E[y', lane]
        float u = (lane < KK) ? 1.f : 0.f;
        if (lane < KK) U[lane] = 1.f;
        float pcur = Ps[ll];
        for (int i = 1; i < MM; ++i) {
            float tv = (lane < KK) ? u * pcur : 0.f;
            pcur = Ps[i*KP + ll];                     // prefetch row i (used next iter)
            float a0 = 0.f, a1 = 0.f, a2 = 0.f, a3 = 0.f;
            #pragma unroll
            for (int j = 0; j < 24; j += 4) {
                a0 = fmaf(__shfl_sync(0xffffffffu, tv, j+0), Ecol[j+0], a0);
                a1 = fmaf(__shfl_sync(0xffffffffu, tv, j+1), Ecol[j+1], a1);
                a2 = fmaf(__shfl_sync(0xffffffffu, tv, j+2), Ecol[j+2], a2);
                a3 = fmaf(__shfl_sync(0xffffffffu, tv, j+3), Ecol[j+3], a3);
            }
            a0 = fmaf(__shfl_sync(0xffffffffu, tv, 24), Ecol[24], a0);
            a1 = fmaf(__shfl_sync(0xffffffffu, tv, 25), Ecol[25], a1);
            float un = (a0 + a1) + (a2 + a3);
            if ((i & 3) == 0) {                       // exact 2^k renorm, every 4 steps
                unsigned mb = __reduce_max_sync(0xffffffffu, __float_as_uint(un));
                un *= __uint_as_float((254u - (mb >> 23)) << 23);
            }
            u = un;
            if (lane < KK) U[i*KP + lane] = u;
        }
    } else if (wid == 1) {
        const int ll = (lane < KK) ? lane : 0;
        float Erow[KK];
        #pragma unroll
        for (int j = 0; j < KK; ++j) Erow[j] = E[ll*KK + j];   // E[lane, y'']
        float v = (lane < KK) ? 1.f : 0.f;
        if (lane < KK) V[(MM-1)*KP + lane] = 1.f;
        float pcur = Ps[(MM-1)*KP + ll];
        for (int i = MM - 2; i >= 0; --i) {
            float rv = (lane < KK) ? v * pcur : 0.f;
            pcur = Ps[i*KP + ll];                     // prefetch row i (used next iter)
            float a0 = 0.f, a1 = 0.f, a2 = 0.f, a3 = 0.f;
            #pragma unroll
            for (int j = 0; j < 24; j += 4) {
                a0 = fmaf(__shfl_sync(0xffffffffu, rv, j+0), Erow[j+0], a0);
                a1 = fmaf(__shfl_sync(0xffffffffu, rv, j+1), Erow[j+1], a1);
                a2 = fmaf(__shfl_sync(0xffffffffu, rv, j+2), Erow[j+2], a2);
                a3 = fmaf(__shfl_sync(0xffffffffu, rv, j+3), Erow[j+3], a3);
            }
            a0 = fmaf(__shfl_sync(0xffffffffu, rv, 24), Erow[24], a0);
            a1 = fmaf(__shfl_sync(0xffffffffu, rv, 25), Erow[25], a1);
            float vn = (a0 + a1) + (a2 + a3);
            if ((i & 3) == 0) {
                unsigned mb = __reduce_max_sync(0xffffffffu, __float_as_uint(vn));
                int fe = (int)(mb >> 23);
                vn *= __uint_as_float((unsigned)(254 - fe) << 23);
                if (lane == 0) dexp[i] = fe - 127;    // applied exponent e_i (else 0)
            }
            v = vn;
            if (lane < KK) V[i*KP + lane] = v;
        }
    }
    __syncthreads();

    // ---- Residual pass: Rres -> Ps, A -> U, B -> V (in place, warp-strided rows) ----
    for (int i = wid; i < MM; i += NW) {
        float u_ = 0.f, v_ = 0.f, p_ = 0.f, prod = 0.f;
        if (lane < KK) {
            u_ = U[i*KP + lane]; v_ = V[i*KP + lane]; p_ = Ps[i*KP + lane];
            prod = u_ * v_ * p_;
        }
        float z = prod;
        #pragma unroll
        for (int o = 16; o; o >>= 1) z += __shfl_xor_sync(0xffffffffu, z, o);
        float inv = 1.f / z;                           // 1 / z_i
        if (lane < KK) {
            float p1 = prod * inv;
            float oh = (lab[i] == lane) ? 1.f : 0.f;
            float sc = __uint_as_float((unsigned)(127 - dexp[i]) << 23);  // exact 2^-e
            Ps[i*KP + lane] = oh - p1;                 // Rres
            U[i*KP + lane]  = u_ * p_ * inv * sc;      // A
            V[i*KP + lane]  = p_ * v_;                 // B
        }
    }
    __syncthreads();

    float* outw = g_scratch + (size_t)w * OUTSZ;

    // ---- dT: counts - E .* sum_i A[i]^T B[i+1] (packed over b-pairs) ----
    for (int pp = t; pp < (KK*KK)/2; pp += NT) {
        const int a = pp / (KK/2);
        const int q = pp - a * (KK/2);                 // b pair = (2q, 2q+1)
        u64 s2 = 0;
        const float* Ua = U + a;
        const u64*   Vq = (const u64*)(V + 2*q);       // row i at offset i*(KP/2)
        #pragma unroll 4
        for (int i = 0; i < MM - 1; ++i) {
            float uu = Ua[i*KP];
            s2 = ffma2(pk2(uu, uu), Vq[(i+1)*(KP/2)], s2);
        }
        float2 s = upk2(s2);
        const int b0 = 2*q;
        outw[KK*DD + a*KK + b0]     = (float)cnt[a*KK + b0]     - E[a*KK + b0]     * s.x;
        outw[KK*DD + a*KK + b0 + 1] = (float)cnt[a*KK + b0 + 1] - E[a*KK + b0 + 1] * s.y;
    }

    // ---- dw: Rres^T @ x (3 thirds of 128 threads; pairs 5/4/4; LDS.64 broadcast) ----
    {
        const int d     = t & (DD - 1);
        const int third = t >> 7;                      // 0,1,2
        const int p0    = (third == 0) ? 0 : (third == 1 ? 5 : 9);
        const int np    = (third == 0) ? 5 : 4;
        u64 acc[5];
        #pragma unroll
        for (int j = 0; j < 5; ++j) acc[j] = 0;
        const float* xp = x + d;
        for (int i = 0; i < MM; i += 2) {
            float xv0 = __ldg(xp + (size_t)i * DD);    // coalesced across lanes
            float xv1 = __ldg(xp + (size_t)(i+1) * DD);
            u64 xx0 = pk2(xv0, xv0), xx1 = pk2(xv1, xv1);
            const u64* r0 = (const u64*)(Ps + i*KP) + p0;
            const u64* r1 = (const u64*)(Ps + (i+1)*KP) + p0;
            #pragma unroll
            for (int j = 0; j < 5; ++j) {
                if (j < np) {
                    acc[j] = ffma2(r0[j], xx0, acc[j]);
                    acc[j] = ffma2(r1[j], xx1, acc[j]);
                }
            }
        }
        #pragma unroll
        for (int j = 0; j < 5; ++j) {
            if (j < np) {
                float2 f = upk2(acc[j]);
                const int k = 2 * (p0 + j);
                outw[(k)     * DD + d] = f.x;
                outw[(k + 1) * DD + d] = f.y;
            }
        }
    }

    // ---- doorbell: this word's gradients are globally visible ----
    __syncthreads();
    if (t == 0) {
        __threadfence();              // release scratch writes
        atomicAdd(&g_ctr, 1);
    }
}

extern "C" void kernel_launch(void* const* d_in, const int* in_sizes, int n_in,
                              void* d_out, int out_size)
{
    const float* data   = (const float*)d_in[0];
    const int*   labels = (const int*)d_in[1];
    const float* W      = (const float*)d_in[2];
    const float* T      = (const float*)d_in[3];
    float* out = (float*)d_out;

    const size_t smem = SM_TOT * sizeof(float);
    cudaFuncSetAttribute(crf_fused_kernel,
                         cudaFuncAttributeMaxDynamicSharedMemorySize, (int)smem);
    crf_fused_kernel<<<BB + NRED, NT, smem>>>(data, labels, W, T, out);
}

// round 16
// speedup vs baseline: 1.0827x; 1.0324x over previous
#include <cuda_runtime.h>
#include <cuda_bf16.h>

#define KK 26
#define DD 128
#define MM 256
#define BB 512
#define NRED 126         // reducer blocks (126*32 >= 4004 outputs)
#define NT  256          // 8 warps, 2 blocks/SM -> 126 regs/thread (max ILP)
#define KP 28            // padded row stride (8B-aligned rows); 2x93.5KB keeps L1D carveout
#define WPAD 130         // padded W row stride
#define OUTSZ (KK*DD + KK*KK)   // 4004

typedef unsigned long long u64;

__device__ float g_scratch[BB * OUTSZ];   // per-word gradients
__device__ int g_ctr  = 0;                // word-completion doorbell
__device__ int g_done = 0;                // reducer-completion counter

// ---- packed f32x2 helpers (FFMA2 path, sm_100a) ----
__device__ __forceinline__ u64 ffma2(u64 a, u64 b, u64 c) {
    u64 d;
    asm("fma.rn.f32x2 %0, %1, %2, %3;" : "=l"(d) : "l"(a), "l"(b), "l"(c));
    return d;
}
__device__ __forceinline__ u64 pk2(float lo, float hi) {
    u64 r; asm("mov.b64 %0, {%1, %2};" : "=l"(r) : "f"(lo), "f"(hi)); return r;
}
__device__ __forceinline__ float2 upk2(u64 v) {
    float2 f; asm("mov.b64 {%0, %1}, %2;" : "=f"(f.x), "=f"(f.y) : "l"(v)); return f;
}
__device__ __forceinline__ int ld_vol(const int* p) {
    int v; asm volatile("ld.volatile.global.s32 %0, [%1];" : "=r"(v) : "l"(p)); return v;
}

// ---- dynamic shared memory layout (floats) ----
#define SM_PS   0                      // [MM][KP] Ps, later Rres
#define SM_U    (SM_PS + MM*KP)        // [MM][KP] U,  later A
#define SM_V    (SM_U  + MM*KP)        // [MM][KP] V,  later B  (aliases Wsh in phase S)
#define SM_E    (SM_V  + MM*KP)        // [KK*KK]  exp(T)
#define SM_LAB  (SM_E  + KK*KK)        // [MM] int labels
#define SM_DEXP (SM_LAB + MM)          // [MM] int backward scale exponents
#define SM_CNT  (SM_DEXP + MM)         // [KK*KK] int transition counts
#define SM_TOT  (SM_CNT + KK*KK)       // 23368 floats = 93472 bytes

__global__ void __launch_bounds__(NT, 2)
crf_fused_kernel(const float* __restrict__ data,
                 const int* __restrict__ labI,
                 const float* __restrict__ Wg,
                 const float* __restrict__ Tg,
                 float* __restrict__ out)
{
    extern __shared__ float sm[];
    const int t    = threadIdx.x;
    const int lane = t & 31;
    const int wid  = t >> 5;

    // ================= REDUCER BLOCKS =================
    if (blockIdx.x >= BB) {
        if (t == 0) {
            while (ld_vol(&g_ctr) < BB) __nanosleep(200);
        }
        __syncthreads();
        __threadfence();   // acquire: order scratch reads after doorbell

        float* red = sm;   // [8][33]
        const int ws = wid;
        const int og = (blockIdx.x - BB) * 32 + lane;
        float s0 = 0.f, s1 = 0.f, s2 = 0.f, s3 = 0.f;
        if (og < OUTSZ) {
            const float* p = g_scratch + (size_t)ws * 64 * OUTSZ + og;
            #pragma unroll 4
            for (int v = 0; v < 64; v += 4) {
                s0 += p[(size_t)(v + 0) * OUTSZ];
                s1 += p[(size_t)(v + 1) * OUTSZ];
                s2 += p[(size_t)(v + 2) * OUTSZ];
                s3 += p[(size_t)(v + 3) * OUTSZ];
            }
        }
        red[ws * 33 + lane] = (s0 + s1) + (s2 + s3);
        __syncthreads();
        if (ws == 0 && og < OUTSZ) {
            float tot = 0.f;
            #pragma unroll
            for (int j = 0; j < 8; ++j) tot += red[j * 33 + lane];
            out[og] = tot * (1.0f / BB);
        }
        __threadfence();
        __syncthreads();
        if (t == 0) {
            if (atomicAdd(&g_done, 1) == NRED - 1) {   // last reducer resets for replay
                g_ctr  = 0;
                g_done = 0;
            }
        }
        return;
    }

    // ================= WORD BLOCKS =================
    float* Ps  = sm + SM_PS;
    float* U   = sm + SM_U;
    float* V   = sm + SM_V;
    float* Wsh = sm + SM_V;            // alias: W lives here only during phase S
    float* E   = sm + SM_E;
    int*   lab  = (int*)(sm + SM_LAB);
    int*   dexp = (int*)(sm + SM_DEXP);
    int*   cnt  = (int*)(sm + SM_CNT);
    __shared__ int s_is64;

    const int w = blockIdx.x;

    // ---- detect labels dtype (int64 LE -> odd int32 words are zero) ----
    if (t == 0) s_is64 = 1;
    __syncthreads();
    if (labI[2*t + 1] != 0) atomicAnd(&s_is64, 0);

    // ---- init: E = exp(T), W -> padded smem, zero counts + dexp ----
    for (int p = t; p < KK*KK; p += NT) { E[p] = __expf(Tg[p]); cnt[p] = 0; }
    for (int p = t; p < KK*DD; p += NT) Wsh[(p / DD) * WPAD + (p % DD)] = Wg[p];
    for (int p = t; p < MM;    p += NT) dexp[p] = 0;
    __syncthreads();
    const int is64 = s_is64;
    for (int p = t; p < MM; p += NT)
        lab[p] = is64 ? labI[((size_t)w*MM + p) * 2] : labI[(size_t)w*MM + p];
    __syncthreads();
    if (t < MM - 1) atomicAdd(&cnt[lab[t]*KK + lab[t+1]], 1);   // exact int, deterministic

    // ---- Phase S: Ps[i][k] = exp(dot(x[i], W[k])) -- 8 rows per W pass ----
    const float* x = data + (size_t)w * MM * DD;
    {
        const int ll = (lane < KK) ? lane : 0;
        const u64* wr = (const u64*)(Wsh + ll * WPAD);
        const int i0 = wid * 32;
        for (int g = 0; g < 4; ++g) {
            const int ib = i0 + g * 8;
            const double2* xb = (const double2*)(x + (size_t)ib * DD);  // row stride DD/4 double2
            u64 acc[8];
            #pragma unroll
            for (int r = 0; r < 8; ++r) acc[r] = 0;
            #pragma unroll 4
            for (int p = 0; p < DD/4; ++p) {
                u64 w0 = wr[2*p], w1 = wr[2*p + 1];
                #pragma unroll
                for (int r = 0; r < 8; ++r) {
                    double2 v = __ldg(xb + (size_t)r * (DD/4) + p);  // 16B lane-uniform broadcast
                    acc[r] = ffma2((u64)__double_as_longlong(v.x), w0, acc[r]);
                    acc[r] = ffma2((u64)__double_as_longlong(v.y), w1, acc[r]);
                }
            }
            if (lane < KK) {
                #pragma unroll
                for (int r = 0; r < 8; ++r) {
                    float2 f = upk2(acc[r]);
                    Ps[(ib + r)*KP + lane] = __expf(f.x + f.y);
                }
            }
        }
    }
    __syncthreads();   // Ps done; Wsh region now free for V

    // ---- Phase DP: warp0 forward, warp1 backward (linear domain, renorm every 8) ----
    if (wid == 0) {
        const int ll = (lane < KK) ? lane : 0;
        float Ecol[KK];
        #pragma unroll
        for (int j = 0; j < KK; ++j) Ecol[j] = E[j*KK + ll];   // E[y', lane]
        float u = (lane < KK) ? 1.f : 0.f;
        if (lane < KK) U[lane] = 1.f;
        float pcur = Ps[ll];
        for (int i = 1; i < MM; ++i) {
            float tv = (lane < KK) ? u * pcur : 0.f;
            pcur = Ps[i*KP + ll];                     // prefetch row i (used next iter)
            float a0 = 0.f, a1 = 0.f, a2 = 0.f, a3 = 0.f;
            #pragma unroll
            for (int j = 0; j < 24; j += 4) {
                a0 = fmaf(__shfl_sync(0xffffffffu, tv, j+0), Ecol[j+0], a0);
                a1 = fmaf(__shfl_sync(0xffffffffu, tv, j+1), Ecol[j+1], a1);
                a2 = fmaf(__shfl_sync(0xffffffffu, tv, j+2), Ecol[j+2], a2);
                a3 = fmaf(__shfl_sync(0xffffffffu, tv, j+3), Ecol[j+3], a3);
            }
            a0 = fmaf(__shfl_sync(0xffffffffu, tv, 24), Ecol[24], a0);
            a1 = fmaf(__shfl_sync(0xffffffffu, tv, 25), Ecol[25], a1);
            float un = (a0 + a1) + (a2 + a3);
            if ((i & 7) == 0) {                       // exact 2^k renorm, every 8 steps
                unsigned mb = __reduce_max_sync(0xffffffffu, __float_as_uint(un));
                un *= __uint_as_float((254u - (mb >> 23)) << 23);
            }
            u = un;
            if (lane < KK) U[i*KP + lane] = u;
        }
    } else if (wid == 1) {
        const int ll = (lane < KK) ? lane : 0;
        float Erow[KK];
        #pragma unroll
        for (int j = 0; j < KK; ++j) Erow[j] = E[ll*KK + j];   // E[lane, y'']
        float v = (lane < KK) ? 1.f : 0.f;
        if (lane < KK) V[(MM-1)*KP + lane] = 1.f;
        float pcur = Ps[(MM-1)*KP + ll];
        for (int i = MM - 2; i >= 0; --i) {
            float rv = (lane < KK) ? v * pcur : 0.f;
            pcur = Ps[i*KP + ll];                     // prefetch row i (used next iter)
            float a0 = 0.f, a1 = 0.f, a2 = 0.f, a3 = 0.f;
            #pragma unroll
            for (int j = 0; j < 24; j += 4) {
                a0 = fmaf(__shfl_sync(0xffffffffu, rv, j+0), Erow[j+0], a0);
                a1 = fmaf(__shfl_sync(0xffffffffu, rv, j+1), Erow[j+1], a1);
                a2 = fmaf(__shfl_sync(0xffffffffu, rv, j+2), Erow[j+2], a2);
                a3 = fmaf(__shfl_sync(0xffffffffu, rv, j+3), Erow[j+3], a3);
            }
            a0 = fmaf(__shfl_sync(0xffffffffu, rv, 24), Erow[24], a0);
            a1 = fmaf(__shfl_sync(0xffffffffu, rv, 25), Erow[25], a1);
            float vn = (a0 + a1) + (a2 + a3);
            if ((i & 7) == 0) {
                unsigned mb = __reduce_max_sync(0xffffffffu, __float_as_uint(vn));
                int fe = (int)(mb >> 23);
                vn *= __uint_as_float((unsigned)(254 - fe) << 23);
                if (lane == 0) dexp[i] = fe - 127;    // applied exponent e_i (else 0)
            }
            v = vn;
            if (lane < KK) V[i*KP + lane] = v;
        }
    }
    __syncthreads();

    // ---- Residual pass: 2 rows interleaved (ILP-2 shfl reductions) ----
    for (int r = 0; r < 32; r += 2) {
        const int i0r = wid * 32 + r;
        const int i1r = i0r + 1;
        float u0=0.f,v0=0.f,p0=0.f,pr0=0.f, u1=0.f,v1=0.f,p1_=0.f,pr1=0.f;
        if (lane < KK) {
            u0 = U[i0r*KP + lane]; v0 = V[i0r*KP + lane]; p0 = Ps[i0r*KP + lane];
            pr0 = u0 * v0 * p0;
            u1 = U[i1r*KP + lane]; v1 = V[i1r*KP + lane]; p1_ = Ps[i1r*KP + lane];
            pr1 = u1 * v1 * p1_;
        }
        float z0 = pr0, z1 = pr1;
        #pragma unroll
        for (int o = 16; o; o >>= 1) {
            z0 += __shfl_xor_sync(0xffffffffu, z0, o);
            z1 += __shfl_xor_sync(0xffffffffu, z1, o);
        }
        float inv0 = 1.f / z0, inv1 = 1.f / z1;
        if (lane < KK) {
            float sc0 = __uint_as_float((unsigned)(127 - dexp[i0r]) << 23);
            float sc1 = __uint_as_float((unsigned)(127 - dexp[i1r]) << 23);
            float oh0 = (lab[i0r] == lane) ? 1.f : 0.f;
            float oh1 = (lab[i1r] == lane) ? 1.f : 0.f;
            Ps[i0r*KP + lane] = oh0 - pr0 * inv0;
            Ps[i1r*KP + lane] = oh1 - pr1 * inv1;
            U[i0r*KP + lane]  = u0 * p0  * inv0 * sc0;
            U[i1r*KP + lane]  = u1 * p1_ * inv1 * sc1;
            V[i0r*KP + lane]  = p0  * v0;
            V[i1r*KP + lane]  = p1_ * v1;
        }
    }
    __syncthreads();

    float* outw = g_scratch + (size_t)w * OUTSZ;

    // ---- dT: 2 a-values per thread (Vq shared, 2 independent chains) ----
    if (t < 169) {
        const int a = t / 13;                          // 0..12
        const int q = t - a * 13;                      // 0..12 (b pair = 2q, 2q+1)
        u64 s2a = 0, s2b = 0;
        const float* Ua = U + a;
        const float* Ub = U + a + 13;
        const u64*   Vq = (const u64*)(V + 2*q);       // row i at offset i*(KP/2)
        #pragma unroll 4
        for (int i = 0; i < MM - 1; ++i) {
            float ua = Ua[i*KP];
            float ub = Ub[i*KP];
            u64 vv = Vq[(i+1)*(KP/2)];
            s2a = ffma2(pk2(ua, ua), vv, s2a);
            s2b = ffma2(pk2(ub, ub), vv, s2b);
        }
        float2 sa = upk2(s2a), sb = upk2(s2b);
        const int b0 = 2*q;
        const int pa = a*KK + b0, pb = (a+13)*KK + b0;
        outw[KK*DD + pa]     = (float)cnt[pa]     - E[pa]     * sa.x;
        outw[KK*DD + pa + 1] = (float)cnt[pa + 1] - E[pa + 1] * sa.y;
        outw[KK*DD + pb]     = (float)cnt[pb]     - E[pb]     * sb.x;
        outw[KK*DD + pb + 1] = (float)cnt[pb + 1] - E[pb + 1] * sb.y;
    }

    // ---- dw: Rres^T @ x -- 4-row software-pipelined x prefetch ----
    {
        const int d    = t & (DD - 1);
        const int half = t >> 7;                       // 0: pairs 0-6, 1: pairs 7-12
        const int p0   = half * 7;
        const int np   = 7 - half;
        u64 acc[7];
        #pragma unroll
        for (int j = 0; j < 7; ++j) acc[j] = 0;
        const float* xp = x + d;
        float n0 = __ldg(xp + 0*DD), n1 = __ldg(xp + 1*DD);
        float n2 = __ldg(xp + 2*DD), n3 = __ldg(xp + 3*DD);
        for (int i = 0; i < MM; i += 4) {
            float c0 = n0, c1 = n1, c2 = n2, c3 = n3;
            if (i + 4 < MM) {                          // issue next 4 LDGs early (MLP>=4)
                n0 = __ldg(xp + (size_t)(i+4) * DD);
                n1 = __ldg(xp + (size_t)(i+5) * DD);
                n2 = __ldg(xp + (size_t)(i+6) * DD);
                n3 = __ldg(xp + (size_t)(i+7) * DD);
            }
            u64 xx0 = pk2(c0,c0), xx1 = pk2(c1,c1), xx2 = pk2(c2,c2), xx3 = pk2(c3,c3);
            const u64* r0 = (const u64*)(Ps + (i+0)*KP) + p0;
            const u64* r1 = (const u64*)(Ps + (i+1)*KP) + p0;
            const u64* r2 = (const u64*)(Ps + (i+2)*KP) + p0;
            const u64* r3 = (const u64*)(Ps + (i+3)*KP) + p0;
            #pragma unroll
            for (int j = 0; j < 7; ++j) {
                if (j < np) {
                    acc[j] = ffma2(r0[j], xx0, acc[j]);
                    acc[j] = ffma2(r1[j], xx1, acc[j]);
                    acc[j] = ffma2(r2[j], xx2, acc[j]);
                    acc[j] = ffma2(r3[j], xx3, acc[j]);
                }
            }
        }
        #pragma unroll
        for (int j = 0; j < 7; ++j) {
            if (j < np) {
                float2 f = upk2(acc[j]);
                const int k = 2 * (p0 + j);
                outw[(k)     * DD + d] = f.x;
                outw[(k + 1) * DD + d] = f.y;
            }
        }
    }

    // ---- doorbell: this word's gradients are globally visible ----
    __syncthreads();
    if (t == 0) {
        __threadfence();              // release scratch writes
        atomicAdd(&g_ctr, 1);
    }
}

extern "C" void kernel_launch(void* const* d_in, const int* in_sizes, int n_in,
                              void* d_out, int out_size)
{
    const float* data   = (const float*)d_in[0];
    const int*   labels = (const int*)d_in[1];
    const float* W      = (const float*)d_in[2];
    const float* T      = (const float*)d_in[3];
    float* out = (float*)d_out;

    const size_t smem = SM_TOT * sizeof(float);
    cudaFuncSetAttribute(crf_fused_kernel,
                         cudaFuncAttributeMaxDynamicSharedMemorySize, (int)smem);
    crf_fused_kernel<<<BB + NRED, NT, smem>>>(data, labels, W, T, out);
}